// round 4
// baseline (speedup 1.0000x reference)
#include <cuda_runtime.h>
#include <cuda_bf16.h>
#include <math.h>

// Problem constants
#define BATCH 128
#define SEQ   1024
#define INDIM 256
#define MSLOT 64
#define DDIM  128
#define OUTD  128
#define NROWS (BATCH * SEQ)          // 131072
#define NC1   (MSLOT + DDIM)         // 192 combined output cols of phase-1 GEMM

typedef unsigned long long ull;

// ---------------- packed f32x2 helpers (sm_103a FFMA2 path; ptxas won't auto-fuse) ----
__device__ __forceinline__ ull fma2(ull a, ull b, ull c) {
    ull d;
    asm("fma.rn.f32x2 %0, %1, %2, %3;" : "=l"(d) : "l"(a), "l"(b), "l"(c));
    return d;
}
__device__ __forceinline__ ull splat2(float x) {
    ull d; unsigned int u = __float_as_uint(x);
    asm("mov.b64 %0, {%1, %1};" : "=l"(d) : "r"(u));
    return d;
}
__device__ __forceinline__ ull pack2(float lo, float hi) {
    ull d;
    asm("mov.b64 %0, {%1, %2};" : "=l"(d) : "r"(__float_as_uint(lo)), "r"(__float_as_uint(hi)));
    return d;
}
__device__ __forceinline__ float2 unpack2(ull v) {
    unsigned int lo, hi;
    asm("mov.b64 {%0, %1}, %2;" : "=r"(lo), "=r"(hi) : "l"(v));
    return make_float2(__uint_as_float(lo), __uint_as_float(hi));
}

// ---------------- scratch (device globals: allocation-free contract) ----------------
__device__ float  g_Wc[INDIM * NC1];                 // [256][192]: cols 0..63 = Wr@MK^T, 64..191 = Ww
__device__ float  g_bc[NC1];                         // bias: br@MK^T | bw
__device__ float  g_wall[(size_t)NROWS * MSLOT];     // softmax weights, 32 MB
__device__ float2 g_eaall[(size_t)NROWS * DDIM];     // interleaved {sigmoid(v), tanh(v)}, 128 MB
__device__ float  g_rall[(size_t)NROWS * DDIM];      // read vectors r_t, 64 MB

// ---------------- kernel 0: fold MK into weights ----------------
__global__ void prep_kernel(const float* __restrict__ Wr, const float* __restrict__ br,
                            const float* __restrict__ Ww, const float* __restrict__ bw,
                            const float* __restrict__ MK)
{
    int i = blockIdx.x;
    int c = threadIdx.x;           // 0..191
    if (i < INDIM) {
        float v;
        if (c < MSLOT) {
            const float* wr = Wr + (size_t)i * DDIM;
            const float* mk = MK + (size_t)c * DDIM;
            float s = 0.f;
            #pragma unroll 4
            for (int d = 0; d < DDIM; ++d) s = fmaf(wr[d], mk[d], s);
            v = s;
        } else {
            v = Ww[(size_t)i * DDIM + (c - MSLOT)];
        }
        g_Wc[(size_t)i * NC1 + c] = v;
    } else {
        float v;
        if (c < MSLOT) {
            const float* mk = MK + (size_t)c * DDIM;
            float s = 0.f;
            #pragma unroll 4
            for (int d = 0; d < DDIM; ++d) s = fmaf(br[d], mk[d], s);
            v = s;
        } else {
            v = bw[c - MSLOT];
        }
        g_bc[c] = v;
    }
}

// ---------------- kernel 1: fused GEMM (logits|v) + softmax/sigmoid/tanh epilogue ----
// Tile: 64 rows x 192 cols, K=256 in chunks of 32. 256 threads.
// Per thread: 8 rows (as 4 f32x2 row-pairs) x 6 cols, FFMA2 inner loop.
__global__ void __launch_bounds__(256, 2) gemm1_kernel(const float* __restrict__ x)
{
    extern __shared__ float sm[];
    float* xs = sm;               // [32][64]  (k-major, transposed)  8 KB
    float* ws = sm + 32 * 64;     // [32][192]                       24 KB
    float* st = sm;               // [64][192] reused in epilogue    48 KB

    const int tid  = threadIdx.x;
    const int row0 = blockIdx.x * 64;
    const int tc   = tid & 31;          // col group (6 cols each)
    const int tr   = tid >> 5;          // row group (8 rows each)
    const int c0   = tc * 6;

    ull acc2[4][6];                     // rows packed in pairs
    #pragma unroll
    for (int rp = 0; rp < 4; ++rp)
        #pragma unroll
        for (int c = 0; c < 6; ++c) acc2[rp][c] = 0ull;

    float bcv[6];
    #pragma unroll
    for (int u = 0; u < 6; ++u) bcv[u] = g_bc[c0 + u];

    const int lr = tid >> 2;            // x load: row 0..63
    const int lk = (tid & 3) * 8;       // x load: 8 consecutive k

    for (int kb = 0; kb < INDIM; kb += 32) {
        const float4* xg = (const float4*)(x + (size_t)(row0 + lr) * INDIM + kb + lk);
        float4 xa = xg[0], xb = xg[1];
        float4 wv4[6];
        const float4* wg = (const float4*)(g_Wc + (size_t)kb * NC1);
        #pragma unroll
        for (int u = 0; u < 6; ++u) wv4[u] = wg[tid + u * 256];

        __syncthreads();   // previous chunk compute done
        xs[(lk + 0) * 64 + lr] = xa.x;
        xs[(lk + 1) * 64 + lr] = xa.y;
        xs[(lk + 2) * 64 + lr] = xa.z;
        xs[(lk + 3) * 64 + lr] = xa.w;
        xs[(lk + 4) * 64 + lr] = xb.x;
        xs[(lk + 5) * 64 + lr] = xb.y;
        xs[(lk + 6) * 64 + lr] = xb.z;
        xs[(lk + 7) * 64 + lr] = xb.w;
        #pragma unroll
        for (int u = 0; u < 6; ++u) ((float4*)ws)[tid + u * 256] = wv4[u];
        __syncthreads();

        #pragma unroll
        for (int k = 0; k < 32; ++k) {
            // 8 rows of x as 4 packed f32x2 (adjacent rows are adjacent in smem)
            const ull* xp = (const ull*)(xs + k * 64 + tr * 8);
            ull x2[4];
            #pragma unroll
            for (int j = 0; j < 4; ++j) x2[j] = xp[j];
            const float2* wr2 = (const float2*)(ws + k * NC1 + c0);
            float2 w0 = wr2[0], w1 = wr2[1], w2 = wr2[2];
            ull wsp[6] = {splat2(w0.x), splat2(w0.y), splat2(w1.x),
                          splat2(w1.y), splat2(w2.x), splat2(w2.y)};
            #pragma unroll
            for (int rp = 0; rp < 4; ++rp)
                #pragma unroll
                for (int c = 0; c < 6; ++c)
                    acc2[rp][c] = fma2(x2[rp], wsp[c], acc2[rp][c]);
        }
    }
    __syncthreads();  // last compute done; safe to overwrite xs/ws with st

    #pragma unroll
    for (int rp = 0; rp < 4; ++rp) {
        float* s0 = st + (tr * 8 + 2 * rp + 0) * NC1 + c0;
        float* s1 = st + (tr * 8 + 2 * rp + 1) * NC1 + c0;
        #pragma unroll
        for (int c = 0; c < 6; ++c) {
            float2 u = unpack2(acc2[rp][c]);
            s0[c] = u.x + bcv[c];
            s1[c] = u.y + bcv[c];
        }
    }
    __syncthreads();

    // epilogue: warp w handles rows w*8..w*8+7
    const int lane = tid & 31;
    const int wrp  = tid >> 5;
    for (int i = 0; i < 8; ++i) {
        int r = wrp * 8 + i;
        const float* srow = st + r * NC1;
        // softmax over cols 0..63
        float l0 = srow[lane], l1 = srow[32 + lane];
        float mx = fmaxf(l0, l1);
        #pragma unroll
        for (int o = 16; o > 0; o >>= 1) mx = fmaxf(mx, __shfl_xor_sync(0xffffffffu, mx, o));
        float p0 = __expf(l0 - mx), p1 = __expf(l1 - mx);
        float s = p0 + p1;
        #pragma unroll
        for (int o = 16; o > 0; o >>= 1) s += __shfl_xor_sync(0xffffffffu, s, o);
        float inv = __fdividef(1.f, s);
        size_t wbase = (size_t)(row0 + r) * MSLOT;
        g_wall[wbase + lane]      = p0 * inv;
        g_wall[wbase + 32 + lane] = p1 * inv;
        // sigmoid / tanh over cols 64..191, stored interleaved as float2{e, a}
        size_t ebase = (size_t)(row0 + r) * DDIM;
        #pragma unroll
        for (int j = 0; j < 4; ++j) {
            int c = j * 32 + lane;
            float v  = srow[MSLOT + c];
            float ez = __expf(-v);
            float sg = __fdividef(1.f, 1.f + ez);
            float u2 = __expf(-2.f * fabsf(v));
            float th = copysignf(__fdividef(1.f - u2, 1.f + u2), v);
            g_eaall[ebase + c] = make_float2(sg, th);
        }
    }
}

// ---------------- kernel 2: sequential memory scan ----------------
// One CTA per batch. 256 threads: d = tid&127, half = tid>>7.
// Mv as 16 packed f32x2 regs (adjacent m-slots). Identity: Mv += w*(a - e*Mv).
// One __syncthreads per step. w via 4-deep smem ring, {e,a} float2 4-deep prefetch.
__device__ __forceinline__ void scan_step(
    int t, int tid, int d, int half,
    float (&wbuf)[4][64], float (&rbuf)[2][128], ull (&Mv2)[16],
    float2& ea_t, float& pw, float& r_carry,
    const float* __restrict__ wp, const float2* __restrict__ eap,
    float* __restrict__ rp)
{
    // flush r of step t-1 (written to rbuf by half==1 last step, sync'd)
    if (half == 0 && t > 0) {
        float rv = r_carry + rbuf[(t - 1) & 1][d];
        rp[(size_t)(t - 1) * DDIM + d] = rv;
    }
    // stage w for step t+2, prefetch w for step t+4 (pw alternates even/odd -> dist 2)
    if (tid < 64) {
        wbuf[(t + 2) & 3][tid] = pw;
        int tn = t + 4; if (tn > SEQ - 1) tn = SEQ - 1;
        pw = wp[(size_t)tn * MSLOT + tid];
    }
    const ull en2 = splat2(-ea_t.x);   // {-e,-e}
    const ull a2  = splat2( ea_t.y);   // { a, a}
    // r + Mv update, packed: r += w*Mv_old ; Mv += w*(a - e*Mv_old)
    ull rA = 0ull, rB = 0ull, rC = 0ull, rD = 0ull;
    const ull* w2 = (const ull*)&wbuf[t & 3][half * 32];   // 16 packed slot-pairs
    #pragma unroll
    for (int j = 0; j < 4; ++j) {
        {
            ull wv = w2[j * 4 + 0], mv = Mv2[j * 4 + 0];
            rA = fma2(wv, mv, rA);
            Mv2[j * 4 + 0] = fma2(wv, fma2(mv, en2, a2), mv);
        }
        {
            ull wv = w2[j * 4 + 1], mv = Mv2[j * 4 + 1];
            rB = fma2(wv, mv, rB);
            Mv2[j * 4 + 1] = fma2(wv, fma2(mv, en2, a2), mv);
        }
        {
            ull wv = w2[j * 4 + 2], mv = Mv2[j * 4 + 2];
            rC = fma2(wv, mv, rC);
            Mv2[j * 4 + 2] = fma2(wv, fma2(mv, en2, a2), mv);
        }
        {
            ull wv = w2[j * 4 + 3], mv = Mv2[j * 4 + 3];
            rD = fma2(wv, mv, rD);
            Mv2[j * 4 + 3] = fma2(wv, fma2(mv, en2, a2), mv);
        }
    }
    float2 uA = unpack2(rA), uB = unpack2(rB), uC = unpack2(rC), uD = unpack2(rD);
    float racc = ((uA.x + uA.y) + (uB.x + uB.y)) + ((uC.x + uC.y) + (uD.x + uD.y));
    if (half) rbuf[t & 1][d] = racc; else r_carry = racc;
    // refill {e,a} slot for step t+4 (consumed then, ~4 steps of latency cover)
    {
        int tn = t + 4; if (tn > SEQ - 1) tn = SEQ - 1;
        ea_t = eap[(size_t)tn * DDIM + d];
    }
    __syncthreads();
}

__global__ void __launch_bounds__(256, 1) scan_kernel(const float* __restrict__ MV)
{
    const int b    = blockIdx.x;
    const int tid  = threadIdx.x;
    const int d    = tid & 127;
    const int half = tid >> 7;

    __shared__ __align__(16) float wbuf[4][64];
    __shared__ __align__(16) float rbuf[2][128];

    ull Mv2[16];
    #pragma unroll
    for (int j = 0; j < 16; ++j)
        Mv2[j] = pack2(MV[(size_t)(half * 32 + 2 * j + 0) * DDIM + d],
                       MV[(size_t)(half * 32 + 2 * j + 1) * DDIM + d]);

    const float*  wp  = g_wall  + (size_t)b * SEQ * MSLOT;
    const float2* eap = g_eaall + (size_t)b * SEQ * DDIM;
    float*        rp  = g_rall  + (size_t)b * SEQ * DDIM;

    float2 eaS[4];
    #pragma unroll
    for (int s = 0; s < 4; ++s)
        eaS[s] = eap[(size_t)s * DDIM + d];

    float pw0 = 0.f, pw1 = 0.f;
    if (tid < 64) {
        wbuf[0][tid] = wp[0 * MSLOT + tid];
        wbuf[1][tid] = wp[1 * MSLOT + tid];
        pw0 = wp[2 * MSLOT + tid];
        pw1 = wp[3 * MSLOT + tid];
    }
    float r_carry = 0.f;
    __syncthreads();

    for (int t = 0; t < SEQ; t += 4) {
        scan_step(t + 0, tid, d, half, wbuf, rbuf, Mv2, eaS[0], pw0, r_carry, wp, eap, rp);
        scan_step(t + 1, tid, d, half, wbuf, rbuf, Mv2, eaS[1], pw1, r_carry, wp, eap, rp);
        scan_step(t + 2, tid, d, half, wbuf, rbuf, Mv2, eaS[2], pw0, r_carry, wp, eap, rp);
        scan_step(t + 3, tid, d, half, wbuf, rbuf, Mv2, eaS[3], pw1, r_carry, wp, eap, rp);
    }
    // flush last step's r
    if (half == 0) {
        float rv = r_carry + rbuf[(SEQ - 1) & 1][d];
        rp[(size_t)(SEQ - 1) * DDIM + d] = rv;
    }
}

// ---------------- kernel 3: readout GEMM Y = sigmoid(R @ Wp + bp) ----------------
// Tile 64 rows x 128 cols, K=128 in chunks of 32. Rows packed in f32x2 pairs.
__global__ void __launch_bounds__(256, 2) gemm2_kernel(const float* __restrict__ Wp,
                                                       const float* __restrict__ bp,
                                                       float* __restrict__ out)
{
    __shared__ __align__(16) float xs[32 * 64];
    __shared__ __align__(16) float ws[32 * 128];

    const int tid  = threadIdx.x;
    const int row0 = blockIdx.x * 64;
    const int tc   = tid & 31;
    const int tr   = tid >> 5;
    const int c0   = tc * 4;

    ull acc2[4][4];
    #pragma unroll
    for (int rp = 0; rp < 4; ++rp)
        #pragma unroll
        for (int c = 0; c < 4; ++c) acc2[rp][c] = 0ull;

    float bpv[4];
    #pragma unroll
    for (int u = 0; u < 4; ++u) bpv[u] = bp[c0 + u];

    const int lr = tid >> 2;
    const int lk = (tid & 3) * 8;

    for (int kb = 0; kb < DDIM; kb += 32) {
        const float4* xg = (const float4*)(g_rall + (size_t)(row0 + lr) * DDIM + kb + lk);
        float4 xa = xg[0], xb = xg[1];
        float4 wv4[4];
        const float4* wg = (const float4*)(Wp + (size_t)kb * OUTD);
        #pragma unroll
        for (int u = 0; u < 4; ++u) wv4[u] = wg[tid + u * 256];

        __syncthreads();
        xs[(lk + 0) * 64 + lr] = xa.x;
        xs[(lk + 1) * 64 + lr] = xa.y;
        xs[(lk + 2) * 64 + lr] = xa.z;
        xs[(lk + 3) * 64 + lr] = xa.w;
        xs[(lk + 4) * 64 + lr] = xb.x;
        xs[(lk + 5) * 64 + lr] = xb.y;
        xs[(lk + 6) * 64 + lr] = xb.z;
        xs[(lk + 7) * 64 + lr] = xb.w;
        #pragma unroll
        for (int u = 0; u < 4; ++u) ((float4*)ws)[tid + u * 256] = wv4[u];
        __syncthreads();

        #pragma unroll
        for (int k = 0; k < 32; ++k) {
            const ull* xp = (const ull*)(xs + k * 64 + tr * 8);
            ull x2[4];
            #pragma unroll
            for (int j = 0; j < 4; ++j) x2[j] = xp[j];
            float4 w4 = *(const float4*)(ws + k * OUTD + c0);
            ull wsp[4] = {splat2(w4.x), splat2(w4.y), splat2(w4.z), splat2(w4.w)};
            #pragma unroll
            for (int rp = 0; rp < 4; ++rp)
                #pragma unroll
                for (int c = 0; c < 4; ++c)
                    acc2[rp][c] = fma2(x2[rp], wsp[c], acc2[rp][c]);
        }
    }

    #pragma unroll
    for (int rp = 0; rp < 4; ++rp) {
        float4 y0, y1;
        float2 u0 = unpack2(acc2[rp][0]);
        float2 u1 = unpack2(acc2[rp][1]);
        float2 u2 = unpack2(acc2[rp][2]);
        float2 u3 = unpack2(acc2[rp][3]);
        y0.x = __fdividef(1.f, 1.f + __expf(-(u0.x + bpv[0])));
        y0.y = __fdividef(1.f, 1.f + __expf(-(u1.x + bpv[1])));
        y0.z = __fdividef(1.f, 1.f + __expf(-(u2.x + bpv[2])));
        y0.w = __fdividef(1.f, 1.f + __expf(-(u3.x + bpv[3])));
        y1.x = __fdividef(1.f, 1.f + __expf(-(u0.y + bpv[0])));
        y1.y = __fdividef(1.f, 1.f + __expf(-(u1.y + bpv[1])));
        y1.z = __fdividef(1.f, 1.f + __expf(-(u2.y + bpv[2])));
        y1.w = __fdividef(1.f, 1.f + __expf(-(u3.y + bpv[3])));
        *(float4*)(out + (size_t)(row0 + tr * 8 + 2 * rp + 0) * OUTD + c0) = y0;
        *(float4*)(out + (size_t)(row0 + tr * 8 + 2 * rp + 1) * OUTD + c0) = y1;
    }
}

// ---------------- launch ----------------
extern "C" void kernel_launch(void* const* d_in, const int* in_sizes, int n_in,
                              void* d_out, int out_size)
{
    const float* x  = (const float*)d_in[0];   // (128,1024,256)
    const float* MK = (const float*)d_in[1];   // (64,128)
    const float* MV = (const float*)d_in[2];   // (64,128)
    const float* Wr = (const float*)d_in[3];   // (256,128)
    const float* br = (const float*)d_in[4];   // (128)
    const float* Ww = (const float*)d_in[5];   // (256,128)
    const float* bw = (const float*)d_in[6];   // (128)
    const float* Wp = (const float*)d_in[7];   // (128,128)
    const float* bp = (const float*)d_in[8];   // (128)
    float* out = (float*)d_out;                // (128,1024,128)

    prep_kernel<<<INDIM + 1, NC1>>>(Wr, br, Ww, bw, MK);
    gemm1_kernel<<<NROWS / 64, 256, 64 * NC1 * (int)sizeof(float)>>>(x);
    scan_kernel<<<BATCH, 256>>>(MV);
    gemm2_kernel<<<NROWS / 64, 256>>>(Wp, bp, out);
}

// round 8
// speedup vs baseline: 1.2357x; 1.2357x over previous
#include <cuda_runtime.h>
#include <cuda_bf16.h>
#include <math.h>

// Problem constants
#define BATCH 128
#define SEQ   1024
#define INDIM 256
#define MSLOT 64
#define DDIM  128
#define OUTD  128
#define NROWS (BATCH * SEQ)          // 131072
#define NC1   (MSLOT + DDIM)         // 192 combined output cols of phase-1 GEMM

typedef unsigned long long ull;

// ---------------- packed f32x2 helpers (sm_103a FFMA2 path; ptxas won't auto-fuse) ----
__device__ __forceinline__ ull fma2(ull a, ull b, ull c) {
    ull d;
    asm("fma.rn.f32x2 %0, %1, %2, %3;" : "=l"(d) : "l"(a), "l"(b), "l"(c));
    return d;
}
__device__ __forceinline__ ull splat2(float x) {
    ull d; unsigned int u = __float_as_uint(x);
    asm("mov.b64 %0, {%1, %1};" : "=l"(d) : "r"(u));
    return d;
}
__device__ __forceinline__ ull pack2(float lo, float hi) {
    ull d;
    asm("mov.b64 %0, {%1, %2};" : "=l"(d) : "r"(__float_as_uint(lo)), "r"(__float_as_uint(hi)));
    return d;
}
__device__ __forceinline__ float2 unpack2(ull v) {
    unsigned int lo, hi;
    asm("mov.b64 {%0, %1}, %2;" : "=r"(lo), "=r"(hi) : "l"(v));
    return make_float2(__uint_as_float(lo), __uint_as_float(hi));
}

// ---------------- scratch (device globals: allocation-free contract) ----------------
__device__ float  g_Wc[INDIM * NC1];                 // [256][192]: cols 0..63 = Wr@MK^T, 64..191 = Ww
__device__ float  g_bc[NC1];                         // bias: br@MK^T | bw
__device__ float  g_wall[(size_t)NROWS * MSLOT];     // softmax weights, 32 MB
__device__ float2 g_eaall[(size_t)NROWS * DDIM];     // interleaved {sigmoid(v), tanh(v)}, 128 MB
__device__ float  g_r0[(size_t)NROWS * DDIM];        // partial r (slots 0..31), 64 MB
__device__ float  g_r1[(size_t)NROWS * DDIM];        // partial r (slots 32..63), 64 MB

// ---------------- kernel 0: fold MK into weights ----------------
__global__ void prep_kernel(const float* __restrict__ Wr, const float* __restrict__ br,
                            const float* __restrict__ Ww, const float* __restrict__ bw,
                            const float* __restrict__ MK)
{
    int i = blockIdx.x;
    int c = threadIdx.x;           // 0..191
    if (i < INDIM) {
        float v;
        if (c < MSLOT) {
            const float* wr = Wr + (size_t)i * DDIM;
            const float* mk = MK + (size_t)c * DDIM;
            float s = 0.f;
            #pragma unroll 4
            for (int d = 0; d < DDIM; ++d) s = fmaf(wr[d], mk[d], s);
            v = s;
        } else {
            v = Ww[(size_t)i * DDIM + (c - MSLOT)];
        }
        g_Wc[(size_t)i * NC1 + c] = v;
    } else {
        float v;
        if (c < MSLOT) {
            const float* mk = MK + (size_t)c * DDIM;
            float s = 0.f;
            #pragma unroll 4
            for (int d = 0; d < DDIM; ++d) s = fmaf(br[d], mk[d], s);
            v = s;
        } else {
            v = bw[c - MSLOT];
        }
        g_bc[c] = v;
    }
}

// ---------------- kernel 1: fused GEMM (logits|v) + softmax/sigmoid/tanh epilogue ----
// Tile: 64 rows x 192 cols, K=256 in chunks of 32. 256 threads.
// Per thread: 8 rows (4 f32x2 row-pairs) x 6 cols, FFMA2 inner loop.
__global__ void __launch_bounds__(256, 2) gemm1_kernel(const float* __restrict__ x)
{
    extern __shared__ float sm[];
    float* xs = sm;               // [32][64]  (k-major, transposed)  8 KB
    float* ws = sm + 32 * 64;     // [32][192]                       24 KB
    float* st = sm;               // [64][192] reused in epilogue    48 KB

    const int tid  = threadIdx.x;
    const int row0 = blockIdx.x * 64;
    const int tc   = tid & 31;          // col group (6 cols each)
    const int tr   = tid >> 5;          // row group (8 rows each)
    const int c0   = tc * 6;

    ull acc2[4][6];                     // rows packed in pairs
    #pragma unroll
    for (int rp = 0; rp < 4; ++rp)
        #pragma unroll
        for (int c = 0; c < 6; ++c) acc2[rp][c] = 0ull;

    float bcv[6];
    #pragma unroll
    for (int u = 0; u < 6; ++u) bcv[u] = g_bc[c0 + u];

    const int lr = tid >> 2;            // x load: row 0..63
    const int lk = (tid & 3) * 8;       // x load: 8 consecutive k

    for (int kb = 0; kb < INDIM; kb += 32) {
        const float4* xg = (const float4*)(x + (size_t)(row0 + lr) * INDIM + kb + lk);
        float4 xa = xg[0], xb = xg[1];
        float4 wv4[6];
        const float4* wg = (const float4*)(g_Wc + (size_t)kb * NC1);
        #pragma unroll
        for (int u = 0; u < 6; ++u) wv4[u] = wg[tid + u * 256];

        __syncthreads();   // previous chunk compute done
        xs[(lk + 0) * 64 + lr] = xa.x;
        xs[(lk + 1) * 64 + lr] = xa.y;
        xs[(lk + 2) * 64 + lr] = xa.z;
        xs[(lk + 3) * 64 + lr] = xa.w;
        xs[(lk + 4) * 64 + lr] = xb.x;
        xs[(lk + 5) * 64 + lr] = xb.y;
        xs[(lk + 6) * 64 + lr] = xb.z;
        xs[(lk + 7) * 64 + lr] = xb.w;
        #pragma unroll
        for (int u = 0; u < 6; ++u) ((float4*)ws)[tid + u * 256] = wv4[u];
        __syncthreads();

        #pragma unroll
        for (int k = 0; k < 32; ++k) {
            // 8 rows of x as 4 packed f32x2, via two 16B broadcast loads
            const ulonglong2* xp = (const ulonglong2*)(xs + k * 64 + tr * 8);
            ulonglong2 xA = xp[0], xB = xp[1];
            ull x2[4] = {xA.x, xA.y, xB.x, xB.y};
            const float2* wr2 = (const float2*)(ws + k * NC1 + c0);
            float2 w0 = wr2[0], w1 = wr2[1], w2 = wr2[2];
            ull wsp[6] = {splat2(w0.x), splat2(w0.y), splat2(w1.x),
                          splat2(w1.y), splat2(w2.x), splat2(w2.y)};
            #pragma unroll
            for (int rp = 0; rp < 4; ++rp)
                #pragma unroll
                for (int c = 0; c < 6; ++c)
                    acc2[rp][c] = fma2(x2[rp], wsp[c], acc2[rp][c]);
        }
    }
    __syncthreads();  // last compute done; safe to overwrite xs/ws with st

    #pragma unroll
    for (int rp = 0; rp < 4; ++rp) {
        float* s0 = st + (tr * 8 + 2 * rp + 0) * NC1 + c0;
        float* s1 = st + (tr * 8 + 2 * rp + 1) * NC1 + c0;
        #pragma unroll
        for (int c = 0; c < 6; ++c) {
            float2 u = unpack2(acc2[rp][c]);
            s0[c] = u.x + bcv[c];
            s1[c] = u.y + bcv[c];
        }
    }
    __syncthreads();

    // epilogue: warp w handles rows w*8..w*8+7
    const int lane = tid & 31;
    const int wrp  = tid >> 5;
    for (int i = 0; i < 8; ++i) {
        int r = wrp * 8 + i;
        const float* srow = st + r * NC1;
        // softmax over cols 0..63
        float l0 = srow[lane], l1 = srow[32 + lane];
        float mx = fmaxf(l0, l1);
        #pragma unroll
        for (int o = 16; o > 0; o >>= 1) mx = fmaxf(mx, __shfl_xor_sync(0xffffffffu, mx, o));
        float p0 = __expf(l0 - mx), p1 = __expf(l1 - mx);
        float s = p0 + p1;
        #pragma unroll
        for (int o = 16; o > 0; o >>= 1) s += __shfl_xor_sync(0xffffffffu, s, o);
        float inv = __fdividef(1.f, s);
        size_t wbase = (size_t)(row0 + r) * MSLOT;
        g_wall[wbase + lane]      = p0 * inv;
        g_wall[wbase + 32 + lane] = p1 * inv;
        // sigmoid / tanh over cols 64..191, stored interleaved as float2{e, a}
        size_t ebase = (size_t)(row0 + r) * DDIM;
        #pragma unroll
        for (int j = 0; j < 4; ++j) {
            int c = j * 32 + lane;
            float v  = srow[MSLOT + c];
            float ez = __expf(-v);
            float sg = __fdividef(1.f, 1.f + ez);
            float u2 = __expf(-2.f * fabsf(v));
            float th = copysignf(__fdividef(1.f - u2, 1.f + u2), v);
            g_eaall[ebase + c] = make_float2(sg, th);
        }
    }
}

// ---------------- kernel 2: sequential memory scan ----------------
// One CTA per batch. 256 threads: d = tid&127, half = tid>>7.
// Mv as 16 packed f32x2 regs. Identity: Mv += w*(a - e*Mv).
// r written as per-half PARTIALS to g_r0/g_r1 (summed in gemm2) -> no per-step
// cross-thread dependency. w via 16-slot smem ring, staged 4 steps per
// __syncthreads (256 barriers total), prefetch distance 4 steps (~800 cyc).
__global__ void __launch_bounds__(256, 1) scan_kernel(const float* __restrict__ MV)
{
    const int b    = blockIdx.x;
    const int tid  = threadIdx.x;
    const int d    = tid & 127;
    const int half = tid >> 7;

    __shared__ __align__(16) float wring[16][64];   // 4 KB, 4 groups of 4 steps

    ull Mv2[16];
    #pragma unroll
    for (int j = 0; j < 16; ++j)
        Mv2[j] = pack2(MV[(size_t)(half * 32 + 2 * j + 0) * DDIM + d],
                       MV[(size_t)(half * 32 + 2 * j + 1) * DDIM + d]);

    const float*  wp  = g_wall  + (size_t)b * SEQ * MSLOT;
    const float2* eap = g_eaall + (size_t)b * SEQ * DDIM;
    float*        rp  = (half ? g_r1 : g_r0) + (size_t)b * SEQ * DDIM;

    float2 eaS[4];
    #pragma unroll
    for (int s = 0; s < 4; ++s)
        eaS[s] = eap[(size_t)s * DDIM + d];

    float pw[4];
    if (tid < 64) {
        #pragma unroll
        for (int i = 0; i < 8; ++i) wring[i][tid] = wp[(size_t)i * MSLOT + tid];   // groups 0,1
        #pragma unroll
        for (int i = 0; i < 4; ++i) pw[i] = wp[(size_t)(8 + i) * MSLOT + tid];     // group 2
    }
    __syncthreads();

    for (int g = 0; g < SEQ / 4; ++g) {
        const int t0 = g * 4;
        // stage group g+2 into ring, prefetch group g+3 into regs
        if (tid < 64) {
            #pragma unroll
            for (int i = 0; i < 4; ++i) wring[(t0 + 8 + i) & 15][tid] = pw[i];
            #pragma unroll
            for (int i = 0; i < 4; ++i) {
                int tn = t0 + 12 + i; if (tn > SEQ - 1) tn = SEQ - 1;
                pw[i] = wp[(size_t)tn * MSLOT + tid];
            }
        }
        #pragma unroll
        for (int i = 0; i < 4; ++i) {
            const int t = t0 + i;
            const ull en2 = splat2(-eaS[i].x);   // {-e,-e}
            const ull a2  = splat2( eaS[i].y);   // { a, a}
            ull r4[4] = {0ull, 0ull, 0ull, 0ull};
            const ulonglong2* w4p = (const ulonglong2*)&wring[t & 15][half * 32];
            #pragma unroll
            for (int j = 0; j < 8; ++j) {
                ulonglong2 wv2 = w4p[j];
                {
                    ull mv = Mv2[2 * j + 0];
                    r4[(2 * j + 0) & 3] = fma2(wv2.x, mv, r4[(2 * j + 0) & 3]);
                    Mv2[2 * j + 0] = fma2(wv2.x, fma2(mv, en2, a2), mv);
                }
                {
                    ull mv = Mv2[2 * j + 1];
                    r4[(2 * j + 1) & 3] = fma2(wv2.y, mv, r4[(2 * j + 1) & 3]);
                    Mv2[2 * j + 1] = fma2(wv2.y, fma2(mv, en2, a2), mv);
                }
            }
            float2 uA = unpack2(r4[0]), uB = unpack2(r4[1]);
            float2 uC = unpack2(r4[2]), uD = unpack2(r4[3]);
            float racc = ((uA.x + uA.y) + (uB.x + uB.y)) + ((uC.x + uC.y) + (uD.x + uD.y));
            rp[(size_t)t * DDIM + d] = racc;                 // partial r, no sync needed
            // refill {e,a} for step t+4
            int tn = t + 4; if (tn > SEQ - 1) tn = SEQ - 1;
            eaS[i] = eap[(size_t)tn * DDIM + d];
        }
        __syncthreads();   // one barrier per 4 steps
    }
}

// ---------------- kernel 3: readout GEMM Y = sigmoid((R0+R1) @ Wp + bp) ----------------
// Tile 64 rows x 128 cols, K=128 in chunks of 32. Rows packed in f32x2 pairs.
__global__ void __launch_bounds__(256, 2) gemm2_kernel(const float* __restrict__ Wp,
                                                       const float* __restrict__ bp,
                                                       float* __restrict__ out)
{
    __shared__ __align__(16) float xs[32 * 64];
    __shared__ __align__(16) float ws[32 * 128];

    const int tid  = threadIdx.x;
    const int row0 = blockIdx.x * 64;
    const int tc   = tid & 31;
    const int tr   = tid >> 5;
    const int c0   = tc * 4;

    ull acc2[4][4];
    #pragma unroll
    for (int rp = 0; rp < 4; ++rp)
        #pragma unroll
        for (int c = 0; c < 4; ++c) acc2[rp][c] = 0ull;

    float bpv[4];
    #pragma unroll
    for (int u = 0; u < 4; ++u) bpv[u] = bp[c0 + u];

    const int lr = tid >> 2;
    const int lk = (tid & 3) * 8;

    for (int kb = 0; kb < DDIM; kb += 32) {
        size_t xidx = (size_t)(row0 + lr) * DDIM + kb + lk;
        const float4* xg0 = (const float4*)(g_r0 + xidx);
        const float4* xg1 = (const float4*)(g_r1 + xidx);
        float4 p0 = xg0[0], p1 = xg0[1], q0 = xg1[0], q1 = xg1[1];
        float4 xa = make_float4(p0.x + q0.x, p0.y + q0.y, p0.z + q0.z, p0.w + q0.w);
        float4 xb = make_float4(p1.x + q1.x, p1.y + q1.y, p1.z + q1.z, p1.w + q1.w);
        float4 wv4[4];
        const float4* wg = (const float4*)(Wp + (size_t)kb * OUTD);
        #pragma unroll
        for (int u = 0; u < 4; ++u) wv4[u] = wg[tid + u * 256];

        __syncthreads();
        xs[(lk + 0) * 64 + lr] = xa.x;
        xs[(lk + 1) * 64 + lr] = xa.y;
        xs[(lk + 2) * 64 + lr] = xa.z;
        xs[(lk + 3) * 64 + lr] = xa.w;
        xs[(lk + 4) * 64 + lr] = xb.x;
        xs[(lk + 5) * 64 + lr] = xb.y;
        xs[(lk + 6) * 64 + lr] = xb.z;
        xs[(lk + 7) * 64 + lr] = xb.w;
        #pragma unroll
        for (int u = 0; u < 4; ++u) ((float4*)ws)[tid + u * 256] = wv4[u];
        __syncthreads();

        #pragma unroll
        for (int k = 0; k < 32; ++k) {
            const ulonglong2* xp = (const ulonglong2*)(xs + k * 64 + tr * 8);
            ulonglong2 xA = xp[0], xB = xp[1];
            ull x2[4] = {xA.x, xA.y, xB.x, xB.y};
            float4 w4 = *(const float4*)(ws + k * OUTD + c0);
            ull wsp[4] = {splat2(w4.x), splat2(w4.y), splat2(w4.z), splat2(w4.w)};
            #pragma unroll
            for (int rp = 0; rp < 4; ++rp)
                #pragma unroll
                for (int c = 0; c < 4; ++c)
                    acc2[rp][c] = fma2(x2[rp], wsp[c], acc2[rp][c]);
        }
    }

    #pragma unroll
    for (int rp = 0; rp < 4; ++rp) {
        float4 y0, y1;
        float2 u0 = unpack2(acc2[rp][0]);
        float2 u1 = unpack2(acc2[rp][1]);
        float2 u2 = unpack2(acc2[rp][2]);
        float2 u3 = unpack2(acc2[rp][3]);
        y0.x = __fdividef(1.f, 1.f + __expf(-(u0.x + bpv[0])));
        y0.y = __fdividef(1.f, 1.f + __expf(-(u1.x + bpv[1])));
        y0.z = __fdividef(1.f, 1.f + __expf(-(u2.x + bpv[2])));
        y0.w = __fdividef(1.f, 1.f + __expf(-(u3.x + bpv[3])));
        y1.x = __fdividef(1.f, 1.f + __expf(-(u0.y + bpv[0])));
        y1.y = __fdividef(1.f, 1.f + __expf(-(u1.y + bpv[1])));
        y1.z = __fdividef(1.f, 1.f + __expf(-(u2.y + bpv[2])));
        y1.w = __fdividef(1.f, 1.f + __expf(-(u3.y + bpv[3])));
        *(float4*)(out + (size_t)(row0 + tr * 8 + 2 * rp + 0) * OUTD + c0) = y0;
        *(float4*)(out + (size_t)(row0 + tr * 8 + 2 * rp + 1) * OUTD + c0) = y1;
    }
}

// ---------------- launch ----------------
extern "C" void kernel_launch(void* const* d_in, const int* in_sizes, int n_in,
                              void* d_out, int out_size)
{
    const float* x  = (const float*)d_in[0];   // (128,1024,256)
    const float* MK = (const float*)d_in[1];   // (64,128)
    const float* MV = (const float*)d_in[2];   // (64,128)
    const float* Wr = (const float*)d_in[3];   // (256,128)
    const float* br = (const float*)d_in[4];   // (128)
    const float* Ww = (const float*)d_in[5];   // (256,128)
    const float* bw = (const float*)d_in[6];   // (128)
    const float* Wp = (const float*)d_in[7];   // (128,128)
    const float* bp = (const float*)d_in[8];   // (128)
    float* out = (float*)d_out;                // (128,1024,128)

    prep_kernel<<<INDIM + 1, NC1>>>(Wr, br, Ww, bw, MK);
    gemm1_kernel<<<NROWS / 64, 256, 64 * NC1 * (int)sizeof(float)>>>(x);
    scan_kernel<<<BATCH, 256>>>(MV);
    gemm2_kernel<<<NROWS / 64, 256>>>(Wp, bp, out);
}